// round 14
// baseline (speedup 1.0000x reference)
#include <cuda_runtime.h>
#include <cstdint>

#define NN 16384
#define HH 2048
#define H4 (HH / 4)            // 512 float4 per row
#define KN 25
#define CHUNK 128
#define C4 (CHUNK / 4)         // 32
#define NCHUNK (HH / CHUNK)    // 16
#define RPW 4
#define NWARPS 8
#define NTHREADS 256
#define RPB (NWARPS * RPW)     // 32 rows per rowgroup
#define NROWBLK (NN / RPB)     // 512 rowgroups
#define NQ 4
#define MAXNC 7
#define SMEM_BYTES (MAXNC * HH * 4)   // 57344
#define NGRID 456              // 152 SMs x 3 resident — single persistent wave
#define RGSTEP (NGRID / NQ)    // 114 rowgroup stride per slice

// NC = noise cols this slice owns; HT = also compute target dot.
// Persistent: loops over rowgroups rg0, rg0+RGSTEP, ... with the tile resident.
template <int NC, bool HT>
__device__ __forceinline__ void run_slice_loop(
    const float* __restrict__ input, const float* __restrict__ weight,
    const float* __restrict__ bias, const float* __restrict__ unig,
    const int* __restrict__ target,
    const float* __restrict__ sw, const float* __restrict__ s_nb,
    const float* __restrict__ s_nu,
    float* __restrict__ out, int rg0, int wid, int lane, int tid, int kbase)
{
    #pragma unroll 1
    for (int rg = rg0; rg < NROWBLK; rg += RGSTEP) {
        const int rb = rg * RPB;

        // slice 0 also emits pnn + pnt for this rowgroup (independent outputs)
        if (kbase == 0) {
            const size_t pnn_base = (size_t)2 * NN + (size_t)NN * KN + (size_t)rb * KN;
            #pragma unroll 1
            for (int i = tid; i < RPB * KN; i += NTHREADS)
                out[pnn_base + i] = s_nu[i % KN];
            if (tid < RPB) {
                int n = rb + tid;
                out[NN + n] = unig[target[n]];
            }
        }

        const int row0 = rb + wid * RPW;

        int tgt[RPW];
        if (HT) {
            #pragma unroll
            for (int r = 0; r < RPW; r++) tgt[r] = target[row0 + r];
        }

        // hoisted, incremented row pointers
        const float4* xp[RPW];
        const float4* wtp[RPW];
        #pragma unroll
        for (int r = 0; r < RPW; r++) {
            xp[r] = reinterpret_cast<const float4*>(input) + (size_t)(row0 + r) * H4 + lane;
            if (HT)
                wtp[r] = reinterpret_cast<const float4*>(weight) + (size_t)tgt[r] * H4 + lane;
        }

        float acc[RPW][NC];
        float acct[RPW];
        #pragma unroll
        for (int r = 0; r < RPW; r++) {
            acct[r] = 0.f;
            #pragma unroll
            for (int j = 0; j < NC; j++) acc[r][j] = 0.f;
        }

        // chunk-0 x prefetch
        float4 x4[RPW];
        #pragma unroll
        for (int r = 0; r < RPW; r++) x4[r] = xp[r][0];

        const float4* wrow = reinterpret_cast<const float4*>(sw) + lane;

        #pragma unroll 2
        for (int c = 0; c < NCHUNK; c++) {
            // prefetch next chunk's x (consumed next iteration) — load-bearing!
            const int dn = (c + 1 < NCHUNK) ? C4 : 0;
            float4 x4n[RPW];
            #pragma unroll
            for (int r = 0; r < RPW; r++) x4n[r] = xp[r][dn];

            float4 wt4[RPW];
            if (HT) {
                #pragma unroll
                for (int r = 0; r < RPW; r++) wt4[r] = wtp[r][0];
            }

            #pragma unroll
            for (int j = 0; j < NC; j++) {
                float4 w = wrow[j * H4];
                #pragma unroll
                for (int r = 0; r < RPW; r++) {
                    float a = acc[r][j];
                    a = fmaf(x4[r].x, w.x, a);
                    a = fmaf(x4[r].y, w.y, a);
                    a = fmaf(x4[r].z, w.z, a);
                    a = fmaf(x4[r].w, w.w, a);
                    acc[r][j] = a;
                }
            }
            if (HT) {
                #pragma unroll
                for (int r = 0; r < RPW; r++) {
                    float a = acct[r];
                    a = fmaf(x4[r].x, wt4[r].x, a);
                    a = fmaf(x4[r].y, wt4[r].y, a);
                    a = fmaf(x4[r].z, wt4[r].z, a);
                    a = fmaf(x4[r].w, wt4[r].w, a);
                    acct[r] = a;
                }
            }

            #pragma unroll
            for (int r = 0; r < RPW; r++) {
                x4[r] = x4n[r];
                xp[r] += C4;
                if (HT) wtp[r] += C4;
            }
            wrow += C4;
        }

        // warp butterfly reduction over lanes (disjoint H slices)
        #pragma unroll
        for (int off = 16; off > 0; off >>= 1) {
            #pragma unroll
            for (int r = 0; r < RPW; r++) {
                if (HT) acct[r] += __shfl_xor_sync(0xffffffffu, acct[r], off);
                #pragma unroll
                for (int j = 0; j < NC; j++)
                    acc[r][j] += __shfl_xor_sync(0xffffffffu, acc[r][j], off);
            }
        }

        // outputs
        #pragma unroll
        for (int r = 0; r < RPW; r++) {
            const int n = row0 + r;
            float* pmn_row = out + (size_t)2 * NN + (size_t)n * KN + kbase;
            #pragma unroll
            for (int j = 0; j < NC; j++) {
                if (lane == j) pmn_row[j] = __expf(acc[r][j] + s_nb[j]);
            }
            if (HT && lane == NC) {
                out[n] = __expf(acct[r] + bias[tgt[r]]);
            }
        }
    }
}

__global__ __launch_bounds__(NTHREADS, 3)
void nce_kernel(const float* __restrict__ input,
                const float* __restrict__ weight,
                const float* __restrict__ bias,
                const float* __restrict__ unig,
                const int* __restrict__ target,
                const int* __restrict__ noise,
                float* __restrict__ out)
{
    extern __shared__ __align__(16) float sw[];   // up to 7 x 2048 noise rows
    __shared__ float s_nb[MAXNC];
    __shared__ float s_nu[KN];
    __shared__ int   s_nk[MAXNC];

    const int tid   = threadIdx.x;
    const int lane  = tid & 31;
    const int wid   = tid >> 5;
    const int bid   = blockIdx.x;
    const int q     = bid & (NQ - 1);
    const int rg0   = bid >> 2;          // 0..113
    const int kbase = (q == 0) ? 0 : (q == 1) ? 7 : (q == 2) ? 14 : 20;
    const int nc    = (q == 0) ? 7 : (q == 1) ? 7 : (q == 2) ? 6 : 5;

    if (tid < nc) {
        int nk = noise[kbase + tid];
        s_nk[tid] = nk;
        s_nb[tid] = bias[nk];
    }
    if (q == 0 && tid < KN) s_nu[tid] = unig[noise[tid]];
    __syncthreads();

    // ---- fill this slice's noise tile into smem ONCE per block ----
    {
        const float4* w4 = reinterpret_cast<const float4*>(weight);
        float4* s4 = reinterpret_cast<float4*>(sw);
        const int total = nc * H4;
        #pragma unroll 1
        for (int idx = tid; idx < total; idx += NTHREADS) {
            int j = idx >> 9;          // / H4
            int h = idx & (H4 - 1);
            s4[idx] = w4[(size_t)s_nk[j] * H4 + h];
        }
    }
    __syncthreads();
    // ======== free-running persistent loop from here ========

    switch (q) {
        case 0: run_slice_loop<7, false>(input, weight, bias, unig, target, sw, s_nb, s_nu, out, rg0, wid, lane, tid, 0);  break;
        case 1: run_slice_loop<7, false>(input, weight, bias, unig, target, sw, s_nb, s_nu, out, rg0, wid, lane, tid, 7);  break;
        case 2: run_slice_loop<6, false>(input, weight, bias, unig, target, sw, s_nb, s_nu, out, rg0, wid, lane, tid, 14); break;
        default: run_slice_loop<5, true>(input, weight, bias, unig, target, sw, s_nb, s_nu, out, rg0, wid, lane, tid, 20); break;
    }
}

extern "C" void kernel_launch(void* const* d_in, const int* in_sizes, int n_in,
                              void* d_out, int out_size) {
    const float* input  = (const float*)d_in[0];
    const float* weight = (const float*)d_in[1];
    const float* bias   = (const float*)d_in[2];
    const float* unig   = (const float*)d_in[3];
    const int*   target = (const int*)d_in[4];
    const int*   noise  = (const int*)d_in[5];
    float* out = (float*)d_out;

    cudaFuncSetAttribute(nce_kernel,
                         cudaFuncAttributeMaxDynamicSharedMemorySize, SMEM_BYTES);
    nce_kernel<<<NGRID, NTHREADS, SMEM_BYTES>>>(input, weight, bias, unig,
                                                target, noise, out);
}

// round 15
// speedup vs baseline: 1.2463x; 1.2463x over previous
#include <cuda_runtime.h>
#include <cstdint>

#define NN 16384
#define HH 2048
#define H4 (HH / 4)            // 512 float4 per row
#define KN 25
#define CHUNK 128
#define C4 (CHUNK / 4)         // 32
#define NCHUNK (HH / CHUNK)    // 16
#define RPW 8
#define NWARPS 4
#define NTHREADS 128
#define RPB (NWARPS * RPW)     // 32 rows per block
#define NROWBLK (NN / RPB)     // 512
#define NQ 4
#define MAXNC 7
#define SMEM_BYTES (MAXNC * HH * 4)   // 57344

// NC = noise cols this quarter owns; HT = also compute target dot
template <int NC, bool HT>
__device__ __forceinline__ void run_quarter(
    const float* __restrict__ input, const float* __restrict__ weight,
    const float* __restrict__ bias, const int* __restrict__ target,
    const float* __restrict__ sw, const float* __restrict__ s_nb,
    float* __restrict__ out, int rb, int wid, int lane, int kbase)
{
    const int row0 = rb + wid * RPW;

    int tgt[RPW];
    if (HT) {
        #pragma unroll
        for (int r = 0; r < RPW; r++) tgt[r] = target[row0 + r];
    }

    // single x base pointer: r*H4 offsets fold into LDG immediates (rows contiguous)
    const float4* xp = reinterpret_cast<const float4*>(input)
                       + (size_t)row0 * H4 + lane;
    const float4* wtp[RPW];
    if (HT) {
        #pragma unroll
        for (int r = 0; r < RPW; r++)
            wtp[r] = reinterpret_cast<const float4*>(weight)
                     + (size_t)tgt[r] * H4 + lane;
    }

    float acc[RPW][NC];
    float acct[RPW];
    #pragma unroll
    for (int r = 0; r < RPW; r++) {
        acct[r] = 0.f;
        #pragma unroll
        for (int j = 0; j < NC; j++) acc[r][j] = 0.f;
    }

    // chunk-0 x prefetch
    float4 x4[RPW];
    #pragma unroll
    for (int r = 0; r < RPW; r++) x4[r] = xp[r * H4];

    const float4* wrow = reinterpret_cast<const float4*>(sw) + lane;

    #pragma unroll 2
    for (int c = 0; c < NCHUNK; c++) {
        // prefetch next chunk's x (consumed next iteration) — load-bearing!
        const int dn = (c + 1 < NCHUNK) ? C4 : 0;
        float4 x4n[RPW];
        #pragma unroll
        for (int r = 0; r < RPW; r++) x4n[r] = xp[r * H4 + dn];

        // target-row weights for THIS chunk: issued now, consumed after
        // the NC smem columns of FFMA -> latency covered
        float4 wt4[RPW];
        if (HT) {
            #pragma unroll
            for (int r = 0; r < RPW; r++) wt4[r] = wtp[r][0];
        }

        #pragma unroll
        for (int j = 0; j < NC; j++) {
            float4 w = wrow[j * H4];
            #pragma unroll
            for (int r = 0; r < RPW; r++) {
                float a = acc[r][j];
                a = fmaf(x4[r].x, w.x, a);
                a = fmaf(x4[r].y, w.y, a);
                a = fmaf(x4[r].z, w.z, a);
                a = fmaf(x4[r].w, w.w, a);
                acc[r][j] = a;
            }
        }
        if (HT) {
            #pragma unroll
            for (int r = 0; r < RPW; r++) {
                float a = acct[r];
                a = fmaf(x4[r].x, wt4[r].x, a);
                a = fmaf(x4[r].y, wt4[r].y, a);
                a = fmaf(x4[r].z, wt4[r].z, a);
                a = fmaf(x4[r].w, wt4[r].w, a);
                acct[r] = a;
            }
        }

        #pragma unroll
        for (int r = 0; r < RPW; r++) {
            x4[r] = x4n[r];
            if (HT) wtp[r] += C4;
        }
        xp += C4;
        wrow += C4;
    }

    // warp butterfly reduction over lanes (disjoint H slices)
    #pragma unroll
    for (int off = 16; off > 0; off >>= 1) {
        #pragma unroll
        for (int r = 0; r < RPW; r++) {
            if (HT) acct[r] += __shfl_xor_sync(0xffffffffu, acct[r], off);
            #pragma unroll
            for (int j = 0; j < NC; j++)
                acc[r][j] += __shfl_xor_sync(0xffffffffu, acc[r][j], off);
        }
    }

    // outputs
    #pragma unroll
    for (int r = 0; r < RPW; r++) {
        const int n = row0 + r;
        float* pmn_row = out + (size_t)2 * NN + (size_t)n * KN + kbase;
        #pragma unroll
        for (int j = 0; j < NC; j++) {
            if (lane == j) pmn_row[j] = __expf(acc[r][j] + s_nb[j]);
        }
        if (HT && lane == NC) {
            out[n] = __expf(acct[r] + bias[tgt[r]]);
        }
    }
}

__global__ __launch_bounds__(NTHREADS, 3)
void nce_kernel(const float* __restrict__ input,
                const float* __restrict__ weight,
                const float* __restrict__ bias,
                const float* __restrict__ unig,
                const int* __restrict__ target,
                const int* __restrict__ noise,
                float* __restrict__ out)
{
    extern __shared__ __align__(16) float sw[];   // up to 7 x 2048 noise rows
    __shared__ float s_nb[MAXNC];
    __shared__ float s_nu[KN];
    __shared__ int   s_nk[MAXNC];

    const int tid   = threadIdx.x;
    const int lane  = tid & 31;
    const int wid   = tid >> 5;
    const int bid   = blockIdx.x;
    const int q     = bid & (NQ - 1);
    const int rb    = (bid >> 2) * RPB;
    const int kbase = (q == 0) ? 0 : (q == 1) ? 7 : (q == 2) ? 14 : 20;
    const int nc    = (q == 0) ? 7 : (q == 1) ? 7 : (q == 2) ? 6 : 5;

    if (tid < nc) {
        int nk = noise[kbase + tid];
        s_nk[tid] = nk;
        s_nb[tid] = bias[nk];
    }
    if (q == 0 && tid < KN) s_nu[tid] = unig[noise[tid]];
    __syncthreads();

    // ---- early independent outputs (quarter 0 only): pnn + pnt ----
    if (q == 0) {
        const size_t pnn_base = (size_t)2 * NN + (size_t)NN * KN + (size_t)rb * KN;
        #pragma unroll 1
        for (int i = tid; i < RPB * KN; i += NTHREADS)
            out[pnn_base + i] = s_nu[i % KN];
        if (tid < RPB) {
            int n = rb + tid;
            out[NN + n] = unig[target[n]];
        }
    }

    // ---- fill this quarter's noise tile into smem (coalesced, once) ----
    {
        const float4* w4 = reinterpret_cast<const float4*>(weight);
        float4* s4 = reinterpret_cast<float4*>(sw);
        const int total = nc * H4;
        #pragma unroll 1
        for (int idx = tid; idx < total; idx += NTHREADS) {
            int j = idx >> 9;          // / H4
            int h = idx & (H4 - 1);
            s4[idx] = w4[(size_t)s_nk[j] * H4 + h];
        }
    }
    __syncthreads();
    // ======== free-running from here ========

    switch (q) {
        case 0: run_quarter<7, false>(input, weight, bias, target, sw, s_nb, out, rb, wid, lane, 0);  break;
        case 1: run_quarter<7, false>(input, weight, bias, target, sw, s_nb, out, rb, wid, lane, 7);  break;
        case 2: run_quarter<6, false>(input, weight, bias, target, sw, s_nb, out, rb, wid, lane, 14); break;
        default: run_quarter<5, true>(input, weight, bias, target, sw, s_nb, out, rb, wid, lane, 20); break;
    }
}

extern "C" void kernel_launch(void* const* d_in, const int* in_sizes, int n_in,
                              void* d_out, int out_size) {
    const float* input  = (const float*)d_in[0];
    const float* weight = (const float*)d_in[1];
    const float* bias   = (const float*)d_in[2];
    const float* unig   = (const float*)d_in[3];
    const int*   target = (const int*)d_in[4];
    const int*   noise  = (const int*)d_in[5];
    float* out = (float*)d_out;

    cudaFuncSetAttribute(nce_kernel,
                         cudaFuncAttributeMaxDynamicSharedMemorySize, SMEM_BYTES);
    nce_kernel<<<NROWBLK * NQ, NTHREADS, SMEM_BYTES>>>(input, weight, bias, unig,
                                                       target, noise, out);
}

// round 16
// speedup vs baseline: 1.4952x; 1.1997x over previous
#include <cuda_runtime.h>
#include <cstdint>

#define NN 16384
#define HH 2048
#define H4 (HH / 4)            // 512 float4 per row
#define KN 25
#define CHUNK 128
#define C4 (CHUNK / 4)         // 32
#define NCHUNK (HH / CHUNK)    // 16
#define RPW 4
#define NWARPS 8
#define NTHREADS 256
#define RPB (NWARPS * RPW)     // 32 rows per block
#define NROWBLK (NN / RPB)     // 512
#define NQ 4
#define MAXNC 7
#define SMEM_BYTES (MAXNC * HH * 4)   // 57344

// NC = noise cols this quarter owns; HT = also compute target dot
template <int NC, bool HT>
__device__ __forceinline__ void run_quarter(
    const float* __restrict__ input, const float* __restrict__ weight,
    const float* __restrict__ bias, const int* __restrict__ target,
    const float* __restrict__ sw, const float* __restrict__ s_nb,
    float* __restrict__ out, int rb, int wid, int lane, int kbase)
{
    const int row0 = rb + wid * RPW;

    int tgt[RPW];
    if (HT) {
        #pragma unroll
        for (int r = 0; r < RPW; r++) tgt[r] = target[row0 + r];
    }

    // hoisted, incremented row pointers (kills per-chunk IMAD chains)
    const float4* xp[RPW];
    const float4* wtp[RPW];
    #pragma unroll
    for (int r = 0; r < RPW; r++) {
        xp[r] = reinterpret_cast<const float4*>(input) + (size_t)(row0 + r) * H4 + lane;
        if (HT)
            wtp[r] = reinterpret_cast<const float4*>(weight) + (size_t)tgt[r] * H4 + lane;
    }

    float acc[RPW][NC];
    float acct[RPW];
    #pragma unroll
    for (int r = 0; r < RPW; r++) {
        acct[r] = 0.f;
        #pragma unroll
        for (int j = 0; j < NC; j++) acc[r][j] = 0.f;
    }

    // chunk-0 x prefetch
    float4 x4[RPW];
    #pragma unroll
    for (int r = 0; r < RPW; r++) x4[r] = xp[r][0];

    const float4* wrow = reinterpret_cast<const float4*>(sw) + lane;

    // LDS pipeline: w for (chunk 0, j=0) preloaded before the loop
    float4 w = wrow[0];

    #pragma unroll 2
    for (int c = 0; c < NCHUNK; c++) {
        // prefetch next chunk's x (consumed next iteration) — load-bearing!
        const int dn = (c + 1 < NCHUNK) ? C4 : 0;
        float4 x4n[RPW];
        #pragma unroll
        for (int r = 0; r < RPW; r++) x4n[r] = xp[r][dn];

        // target-row weights for THIS chunk: issued now, consumed after
        // the NC smem columns of FFMA -> latency covered
        float4 wt4[RPW];
        if (HT) {
            #pragma unroll
            for (int r = 0; r < RPW; r++) wt4[r] = wtp[r][0];
        }

        // w for the first j-block of the NEXT chunk (primes the rotation
        // across the chunk boundary; last chunk re-reads harmlessly)
        const float4* wrow_nx = wrow + dn;

        #pragma unroll
        for (int j = 0; j < NC; j++) {
            // rotate: issue the LDS for j+1 (or next chunk's j=0) now, so it
            // completes under this j-block's 16 FFMAs
            float4 wn = (j + 1 < NC) ? wrow[(j + 1) * H4] : wrow_nx[0];
            #pragma unroll
            for (int r = 0; r < RPW; r++) {
                float a = acc[r][j];
                a = fmaf(x4[r].x, w.x, a);
                a = fmaf(x4[r].y, w.y, a);
                a = fmaf(x4[r].z, w.z, a);
                a = fmaf(x4[r].w, w.w, a);
                acc[r][j] = a;
            }
            w = wn;
        }
        if (HT) {
            #pragma unroll
            for (int r = 0; r < RPW; r++) {
                float a = acct[r];
                a = fmaf(x4[r].x, wt4[r].x, a);
                a = fmaf(x4[r].y, wt4[r].y, a);
                a = fmaf(x4[r].z, wt4[r].z, a);
                a = fmaf(x4[r].w, wt4[r].w, a);
                acct[r] = a;
            }
        }

        #pragma unroll
        for (int r = 0; r < RPW; r++) {
            x4[r] = x4n[r];
            xp[r] += C4;
            if (HT) wtp[r] += C4;
        }
        wrow += C4;
    }

    // warp butterfly reduction over lanes (disjoint H slices)
    #pragma unroll
    for (int off = 16; off > 0; off >>= 1) {
        #pragma unroll
        for (int r = 0; r < RPW; r++) {
            if (HT) acct[r] += __shfl_xor_sync(0xffffffffu, acct[r], off);
            #pragma unroll
            for (int j = 0; j < NC; j++)
                acc[r][j] += __shfl_xor_sync(0xffffffffu, acc[r][j], off);
        }
    }

    // outputs
    #pragma unroll
    for (int r = 0; r < RPW; r++) {
        const int n = row0 + r;
        float* pmn_row = out + (size_t)2 * NN + (size_t)n * KN + kbase;
        #pragma unroll
        for (int j = 0; j < NC; j++) {
            if (lane == j) pmn_row[j] = __expf(acc[r][j] + s_nb[j]);
        }
        if (HT && lane == NC) {
            out[n] = __expf(acct[r] + bias[tgt[r]]);
        }
    }
}

__global__ __launch_bounds__(NTHREADS, 3)
void nce_kernel(const float* __restrict__ input,
                const float* __restrict__ weight,
                const float* __restrict__ bias,
                const float* __restrict__ unig,
                const int* __restrict__ target,
                const int* __restrict__ noise,
                float* __restrict__ out)
{
    extern __shared__ __align__(16) float sw[];   // up to 7 x 2048 noise rows
    __shared__ float s_nb[MAXNC];
    __shared__ float s_nu[KN];
    __shared__ int   s_nk[MAXNC];

    const int tid   = threadIdx.x;
    const int lane  = tid & 31;
    const int wid   = tid >> 5;
    const int bid   = blockIdx.x;
    const int q     = bid & (NQ - 1);
    const int rb    = (bid >> 2) * RPB;
    const int kbase = (q == 0) ? 0 : (q == 1) ? 7 : (q == 2) ? 14 : 20;
    const int nc    = (q == 0) ? 7 : (q == 1) ? 7 : (q == 2) ? 6 : 5;

    if (tid < nc) {
        int nk = noise[kbase + tid];
        s_nk[tid] = nk;
        s_nb[tid] = bias[nk];
    }
    if (q == 0 && tid < KN) s_nu[tid] = unig[noise[tid]];
    __syncthreads();

    // ---- early independent outputs (quarter 0 only): pnn + pnt ----
    if (q == 0) {
        const size_t pnn_base = (size_t)2 * NN + (size_t)NN * KN + (size_t)rb * KN;
        #pragma unroll 1
        for (int i = tid; i < RPB * KN; i += NTHREADS)
            out[pnn_base + i] = s_nu[i % KN];
        if (tid < RPB) {
            int n = rb + tid;
            out[NN + n] = unig[target[n]];
        }
    }

    // ---- fill this quarter's noise tile into smem (coalesced, once) ----
    {
        const float4* w4 = reinterpret_cast<const float4*>(weight);
        float4* s4 = reinterpret_cast<float4*>(sw);
        const int total = nc * H4;
        #pragma unroll 1
        for (int idx = tid; idx < total; idx += NTHREADS) {
            int j = idx >> 9;          // / H4
            int h = idx & (H4 - 1);
            s4[idx] = w4[(size_t)s_nk[j] * H4 + h];
        }
    }
    __syncthreads();
    // ======== free-running from here ========

    switch (q) {
        case 0: run_quarter<7, false>(input, weight, bias, target, sw, s_nb, out, rb, wid, lane, 0);  break;
        case 1: run_quarter<7, false>(input, weight, bias, target, sw, s_nb, out, rb, wid, lane, 7);  break;
        case 2: run_quarter<6, false>(input, weight, bias, target, sw, s_nb, out, rb, wid, lane, 14); break;
        default: run_quarter<5, true>(input, weight, bias, target, sw, s_nb, out, rb, wid, lane, 20); break;
    }
}

extern "C" void kernel_launch(void* const* d_in, const int* in_sizes, int n_in,
                              void* d_out, int out_size) {
    const float* input  = (const float*)d_in[0];
    const float* weight = (const float*)d_in[1];
    const float* bias   = (const float*)d_in[2];
    const float* unig   = (const float*)d_in[3];
    const int*   target = (const int*)d_in[4];
    const int*   noise  = (const int*)d_in[5];
    float* out = (float*)d_out;

    cudaFuncSetAttribute(nce_kernel,
                         cudaFuncAttributeMaxDynamicSharedMemorySize, SMEM_BYTES);
    nce_kernel<<<NROWBLK * NQ, NTHREADS, SMEM_BYTES>>>(input, weight, bias, unig,
                                                       target, noise, out);
}